// round 2
// baseline (speedup 1.0000x reference)
#include <cuda_runtime.h>
#include <math.h>

// Problem constants
#define IN_DIM   256
#define OUT_DIM  256
#define GRIDN    12      // NUM + 1 + 2K = 5+1+6
#define NB       8       // NUM + K = 5+3
#define BATCH    2048
#define BT       8       // batches per block
#define THREADS  512

// Precomputed fused scales, transposed to [o][i] for coalesced per-o slab loads
__device__ float g_sbT[OUT_DIM * IN_DIM];
__device__ float g_ssT[OUT_DIM * IN_DIM];

__global__ void prep_kernel(const float* __restrict__ sb,
                            const float* __restrict__ ssp,
                            const float* __restrict__ mask) {
    int idx = blockIdx.x * blockDim.x + threadIdx.x;   // idx = i*256 + o
    if (idx < IN_DIM * OUT_DIM) {
        int i = idx >> 8;
        int o = idx & 255;
        float m = mask[idx];
        g_sbT[o * IN_DIM + i] = m * sb[idx];
        g_ssT[o * IN_DIM + i] = m * ssp[idx];
    }
}

__global__ void zero_kernel(float* __restrict__ out, int n) {
    int idx = blockIdx.x * blockDim.x + threadIdx.x;
    if (idx < n) out[idx] = 0.f;
}

__global__ __launch_bounds__(THREADS)
void kan_kernel(const float* __restrict__ x,
                const float* __restrict__ grid,
                const float* __restrict__ coef,
                float* __restrict__ out) {
    // Double-buffered per-o staging
    __shared__ float s_coefT[2][NB * IN_DIM];  // [buf][k][i]
    __shared__ float s_sb[2][IN_DIM];
    __shared__ float s_ss[2][IN_DIM];

    const int tid  = threadIdx.x;
    const int bsub = tid >> 6;       // 0..7 -> which batch in the block
    const int quad = tid & 63;       // 0..63 -> which i-quad
    const int i0   = quad << 2;
    const int b    = blockIdx.x * BT + bsub;

    // ---- Phase 0: per-thread B-spline basis for 4 input dims (registers) ----
    float4 x4 = *reinterpret_cast<const float4*>(x + (size_t)b * IN_DIM + i0);
    float xs[4] = {x4.x, x4.y, x4.z, x4.w};

    float bspT[NB][4];   // [k][ii] layout for the per-k FMA sweep
    #pragma unroll
    for (int ii = 0; ii < 4; ii++) {
        const float* gr = grid + (size_t)(i0 + ii) * GRIDN;
        float g[GRIDN];
        #pragma unroll
        for (int j = 0; j < GRIDN; j++) g[j] = gr[j];
        float xv = xs[ii];
        float B[GRIDN - 1];
        #pragma unroll
        for (int j = 0; j < GRIDN - 1; j++)
            B[j] = (xv >= g[j] && xv < g[j + 1]) ? 1.f : 0.f;
        #pragma unroll
        for (int ki = 1; ki <= 3; ki++) {
            #pragma unroll
            for (int j = 0; j < GRIDN - 1 - 3; j++) { /* dummy to keep bounds simple */ }
            #pragma unroll
            for (int j = 0; j < GRIDN - 1; j++) {
                if (j < GRIDN - 1 - ki) {
                    float left  = (xv - g[j]) / (g[j + ki] - g[j]);
                    float right = (g[j + ki + 1] - xv) / (g[j + ki + 1] - g[j + 1]);
                    B[j] = left * B[j] + right * B[j + 1];
                }
            }
        }
        #pragma unroll
        for (int k = 0; k < NB; k++) bspT[k][ii] = B[k];
    }

    float base[4];
    #pragma unroll
    for (int ii = 0; ii < 4; ii++)
        base[ii] = xs[ii] / (1.f + expf(-xs[ii]));

    // ---- Output regions (order: y_sum, preacts, postacts, postspline) ----
    float* ysum     = out;
    float* preacts  = out + (size_t)BATCH * OUT_DIM;
    float* postacts = preacts  + (size_t)BATCH * OUT_DIM * IN_DIM;
    float* postspl  = postacts + (size_t)BATCH * OUT_DIM * IN_DIM;

    const size_t rowbase = (size_t)b * OUT_DIM * IN_DIM + i0;

    // Cooperative per-o fill of coef slab (transposed) + scale rows
    auto fill = [&](int o, int bufI) {
        int i    = tid >> 1;
        int half = tid & 1;
        float4 v = *reinterpret_cast<const float4*>(
            coef + (size_t)i * (OUT_DIM * NB) + (size_t)o * NB + half * 4);
        float* dstT = s_coefT[bufI];
        dstT[(half * 4 + 0) * IN_DIM + i] = v.x;
        dstT[(half * 4 + 1) * IN_DIM + i] = v.y;
        dstT[(half * 4 + 2) * IN_DIM + i] = v.z;
        dstT[(half * 4 + 3) * IN_DIM + i] = v.w;
        if (tid < 64) {
            float4 s = *reinterpret_cast<const float4*>(g_sbT + (size_t)o * IN_DIM + tid * 4);
            *reinterpret_cast<float4*>(&s_sb[bufI][tid * 4]) = s;
        } else if (tid < 128) {
            int t = tid - 64;
            float4 s = *reinterpret_cast<const float4*>(g_ssT + (size_t)o * IN_DIM + t * 4);
            *reinterpret_cast<float4*>(&s_ss[bufI][t * 4]) = s;
        }
    };

    fill(0, 0);

    for (int o = 0; o < OUT_DIM; o++) {
        int buf = o & 1;
        __syncthreads();                 // fill(o) complete; buf^1 reads from o-1 done
        if (o + 1 < OUT_DIM) fill(o + 1, buf ^ 1);

        // Spline dot: y[ii] = sum_k bsp[ii][k] * coef[i0+ii][o][k]
        float4 y4 = make_float4(0.f, 0.f, 0.f, 0.f);
        const float* cT = s_coefT[buf];
        #pragma unroll
        for (int k = 0; k < NB; k++) {
            float4 ck = *reinterpret_cast<const float4*>(cT + k * IN_DIM + i0);
            y4.x += ck.x * bspT[k][0];
            y4.y += ck.y * bspT[k][1];
            y4.z += ck.z * bspT[k][2];
            y4.w += ck.w * bspT[k][3];
        }

        float4 sb4 = *reinterpret_cast<const float4*>(&s_sb[buf][i0]);
        float4 ss4 = *reinterpret_cast<const float4*>(&s_ss[buf][i0]);
        float4 yy4;
        yy4.x = sb4.x * base[0] + ss4.x * y4.x;
        yy4.y = sb4.y * base[1] + ss4.y * y4.y;
        yy4.z = sb4.z * base[2] + ss4.z * y4.z;
        yy4.w = sb4.w * base[3] + ss4.w * y4.w;

        size_t off = rowbase + (size_t)o * IN_DIM;
        *reinterpret_cast<float4*>(postspl  + off) = y4;   // raw spline (pre-scale)
        *reinterpret_cast<float4*>(postacts + off) = yy4;  // scaled+masked
        *reinterpret_cast<float4*>(preacts  + off) = x4;   // broadcast x

        // y_sum: warp covers 128 contiguous i for one (b,o) -> butterfly + 1 atomic
        float s = (yy4.x + yy4.y) + (yy4.z + yy4.w);
        #pragma unroll
        for (int d = 16; d > 0; d >>= 1)
            s += __shfl_xor_sync(0xffffffffu, s, d);
        if ((tid & 31) == 0)
            atomicAdd(ysum + (size_t)b * OUT_DIM + o, s);
    }
}

extern "C" void kernel_launch(void* const* d_in, const int* in_sizes, int n_in,
                              void* d_out, int out_size) {
    const float* x     = (const float*)d_in[0];
    const float* grid  = (const float*)d_in[1];
    const float* coef  = (const float*)d_in[2];
    const float* sb    = (const float*)d_in[3];
    const float* ssp   = (const float*)d_in[4];
    const float* mask  = (const float*)d_in[5];
    float* out = (float*)d_out;

    (void)in_sizes; (void)n_in; (void)out_size;

    // Zero the y_sum region (rest is fully overwritten)
    int nsum = BATCH * OUT_DIM;
    zero_kernel<<<(nsum + 511) / 512, 512>>>(out, nsum);

    // Fuse mask into scales, transpose to [o][i]
    prep_kernel<<<(IN_DIM * OUT_DIM + 255) / 256, 256>>>(sb, ssp, mask);

    // Main fused kernel: 256 blocks x 512 threads, 8 batches per block
    kan_kernel<<<BATCH / BT, THREADS>>>(x, grid, coef, out);
}

// round 3
// speedup vs baseline: 2.1503x; 2.1503x over previous
#include <cuda_runtime.h>
#include <math.h>

#define IN_DIM   256
#define OUT_DIM  256
#define GRIDN    12      // NUM + 1 + 2K
#define NB       8       // NUM + K
#define BATCH    2048
#define BT       8       // batches per block
#define THREADS  256
#define OT       4       // outputs per shared tile
#define NT       (OUT_DIM / OT)

// Fused mask*scale, transposed to [o][i] for coalesced per-o-tile loads
__device__ float g_sbT[OUT_DIM * IN_DIM];
__device__ float g_ssT[OUT_DIM * IN_DIM];

__global__ void prep_kernel(const float* __restrict__ sb,
                            const float* __restrict__ ssp,
                            const float* __restrict__ mask) {
    int idx = blockIdx.x * blockDim.x + threadIdx.x;   // idx = i*256 + o
    if (idx < IN_DIM * OUT_DIM) {
        int i = idx >> 8;
        int o = idx & 255;
        float m = mask[idx];
        g_sbT[o * IN_DIM + i] = m * sb[idx];
        g_ssT[o * IN_DIM + i] = m * ssp[idx];
    }
}

__global__ void zero_kernel(float* __restrict__ out, int n) {
    int idx = blockIdx.x * blockDim.x + threadIdx.x;
    if (idx < n) out[idx] = 0.f;
}

__global__ __launch_bounds__(THREADS, 2)
void kan_kernel(const float* __restrict__ x,
                const float* __restrict__ grid,
                const float* __restrict__ coef,
                float* __restrict__ out) {
    // coef slab for one o-tile: [i][q] where q = ol*8+k, stored as float4-chunks
    // with XOR swizzle qs = qchunk ^ ((i>>2)&7). Row = 32 floats, no pad. 32 KB.
    __shared__ float s_coef[IN_DIM * OT * NB];
    __shared__ float s_sb[OT * IN_DIM];     // 4 KB
    __shared__ float s_ss[OT * IN_DIM];     // 4 KB

    const int tid  = threadIdx.x;
    const int quad = tid & 63;       // i-quad
    const int bg   = tid >> 6;       // 0..3 batch-pair group
    const int i0   = quad << 2;
    const int b0   = blockIdx.x * BT + bg * 2;

    // ---- Prologue: B-spline basis for 2 batches x 4 dims, in registers ----
    float4 x4[2];
    x4[0] = *reinterpret_cast<const float4*>(x + (size_t)b0 * IN_DIM + i0);
    x4[1] = *reinterpret_cast<const float4*>(x + (size_t)(b0 + 1) * IN_DIM + i0);
    float xs[2][4] = {{x4[0].x, x4[0].y, x4[0].z, x4[0].w},
                      {x4[1].x, x4[1].y, x4[1].z, x4[1].w}};

    float bsp[2][NB][4];   // [b][k][ii]
    #pragma unroll
    for (int ii = 0; ii < 4; ii++) {
        const float* gr = grid + (size_t)(i0 + ii) * GRIDN;
        float g[GRIDN];
        #pragma unroll
        for (int j = 0; j < GRIDN; j++) g[j] = gr[j];
        #pragma unroll
        for (int bb = 0; bb < 2; bb++) {
            float xv = xs[bb][ii];
            float B[GRIDN - 1];
            #pragma unroll
            for (int j = 0; j < GRIDN - 1; j++)
                B[j] = (xv >= g[j] && xv < g[j + 1]) ? 1.f : 0.f;
            #pragma unroll
            for (int ki = 1; ki <= 3; ki++) {
                #pragma unroll
                for (int j = 0; j < GRIDN - 1; j++) {
                    if (j < GRIDN - 1 - ki) {
                        float left  = (xv - g[j]) / (g[j + ki] - g[j]);
                        float right = (g[j + ki + 1] - xv) / (g[j + ki + 1] - g[j + 1]);
                        B[j] = left * B[j] + right * B[j + 1];
                    }
                }
            }
            #pragma unroll
            for (int k = 0; k < NB; k++) bsp[bb][k][ii] = B[k];
        }
    }

    float base[2][4];
    #pragma unroll
    for (int bb = 0; bb < 2; bb++)
        #pragma unroll
        for (int ii = 0; ii < 4; ii++) {
            float xv = xs[bb][ii];
            base[bb][ii] = xv / (1.f + __expf(-xv));
        }

    // ---- Output regions (y_sum, preacts, postacts, postspline) ----
    float* ysum     = out;
    float* preacts  = out + (size_t)BATCH * OUT_DIM;
    float* postacts = preacts  + (size_t)BATCH * OUT_DIM * IN_DIM;
    float* postspl  = postacts + (size_t)BATCH * OUT_DIM * IN_DIM;

    const size_t rowbase0 = (size_t)b0 * OUT_DIM * IN_DIM + i0;
    const int mysw = (i0 >> 2) & 7;   // note: (i>>2)&7 is same for ii=0..3 of a quad

    for (int T = 0; T < NT; T++) {
        __syncthreads();   // previous tile's reads complete

        // Fill coef slab: coalesced LDG.128 + swizzled STS.128 (conflict-free)
        #pragma unroll
        for (int r = 0; r < 8; r++) {
            int c = tid + THREADS * r;       // 0..2047
            int i = c >> 3;
            int q = c & 7;                   // float4-chunk within the 32-float row
            float4 v = *reinterpret_cast<const float4*>(
                coef + (size_t)i * (OUT_DIM * NB) + T * (OT * NB) + q * 4);
            int qs = q ^ ((i >> 2) & 7);
            *reinterpret_cast<float4*>(s_coef + i * 32 + (qs << 2)) = v;
        }
        // Fill scales: 1 float4 per thread per array
        {
            int ol = tid >> 6;
            int ic = (tid & 63) << 2;
            int o  = T * OT + ol;
            *reinterpret_cast<float4*>(s_sb + ol * IN_DIM + ic) =
                *reinterpret_cast<const float4*>(g_sbT + (size_t)o * IN_DIM + ic);
            *reinterpret_cast<float4*>(s_ss + ol * IN_DIM + ic) =
                *reinterpret_cast<const float4*>(g_ssT + (size_t)o * IN_DIM + ic);
        }
        __syncthreads();

        #pragma unroll
        for (int ol = 0; ol < OT; ol++) {
            const int o = T * OT + ol;

            float y[2][4];
            #pragma unroll
            for (int bb = 0; bb < 2; bb++)
                #pragma unroll
                for (int ii = 0; ii < 4; ii++) y[bb][ii] = 0.f;

            #pragma unroll
            for (int ii = 0; ii < 4; ii++) {
                const int i = i0 + ii;
                float4 ca = *reinterpret_cast<const float4*>(
                    s_coef + i * 32 + (((2 * ol)     ^ mysw) << 2));
                float4 cb = *reinterpret_cast<const float4*>(
                    s_coef + i * 32 + (((2 * ol + 1) ^ mysw) << 2));
                #pragma unroll
                for (int bb = 0; bb < 2; bb++) {
                    float acc;
                    acc  = ca.x * bsp[bb][0][ii];
                    acc += ca.y * bsp[bb][1][ii];
                    acc += ca.z * bsp[bb][2][ii];
                    acc += ca.w * bsp[bb][3][ii];
                    acc += cb.x * bsp[bb][4][ii];
                    acc += cb.y * bsp[bb][5][ii];
                    acc += cb.z * bsp[bb][6][ii];
                    acc += cb.w * bsp[bb][7][ii];
                    y[bb][ii] = acc;
                }
            }

            float4 sb4 = *reinterpret_cast<const float4*>(s_sb + ol * IN_DIM + i0);
            float4 ss4 = *reinterpret_cast<const float4*>(s_ss + ol * IN_DIM + i0);

            #pragma unroll
            for (int bb = 0; bb < 2; bb++) {
                float4 y4  = make_float4(y[bb][0], y[bb][1], y[bb][2], y[bb][3]);
                float4 yy4;
                yy4.x = sb4.x * base[bb][0] + ss4.x * y4.x;
                yy4.y = sb4.y * base[bb][1] + ss4.y * y4.y;
                yy4.z = sb4.z * base[bb][2] + ss4.z * y4.z;
                yy4.w = sb4.w * base[bb][3] + ss4.w * y4.w;

                size_t off = rowbase0 + (size_t)bb * (OUT_DIM * IN_DIM)
                                      + (size_t)o * IN_DIM;
                *reinterpret_cast<float4*>(postspl  + off) = y4;
                *reinterpret_cast<float4*>(postacts + off) = yy4;
                *reinterpret_cast<float4*>(preacts  + off) = x4[bb];

                // y_sum partial: warp covers 128 contiguous i for (b0+bb, o)
                float s = (yy4.x + yy4.y) + (yy4.z + yy4.w);
                #pragma unroll
                for (int d = 16; d > 0; d >>= 1)
                    s += __shfl_xor_sync(0xffffffffu, s, d);
                if ((tid & 31) == 0)
                    atomicAdd(ysum + (size_t)(b0 + bb) * OUT_DIM + o, s);
            }
        }
    }
}

extern "C" void kernel_launch(void* const* d_in, const int* in_sizes, int n_in,
                              void* d_out, int out_size) {
    const float* x     = (const float*)d_in[0];
    const float* grid  = (const float*)d_in[1];
    const float* coef  = (const float*)d_in[2];
    const float* sb    = (const float*)d_in[3];
    const float* ssp   = (const float*)d_in[4];
    const float* mask  = (const float*)d_in[5];
    float* out = (float*)d_out;

    (void)in_sizes; (void)n_in; (void)out_size;

    int nsum = BATCH * OUT_DIM;
    zero_kernel<<<(nsum + 511) / 512, 512>>>(out, nsum);
    prep_kernel<<<(IN_DIM * OUT_DIM + 255) / 256, 256>>>(sb, ssp, mask);
    kan_kernel<<<BATCH / BT, THREADS>>>(x, grid, coef, out);
}

// round 6
// speedup vs baseline: 2.4327x; 1.1313x over previous
#include <cuda_runtime.h>
#include <cstdint>
#include <math.h>

#define IN_DIM   256
#define OUT_DIM  256
#define GRIDN    12      // NUM + 1 + 2K
#define NB       8       // NUM + K
#define BATCH    2048
#define BT       8       // batches per block
#define THREADS  256
#define OT       4       // outputs per shared tile
#define NT       (OUT_DIM / OT)

// Fused mask*scale, transposed to [o][i]
__device__ float g_sbT[OUT_DIM * IN_DIM];
__device__ float g_ssT[OUT_DIM * IN_DIM];

// Merged zero(y_sum) + scale-prep kernel (2 launches/call total -> ncu -s 5
// lands on kan_kernel)
__global__ void init_kernel(const float* __restrict__ sb,
                            const float* __restrict__ ssp,
                            const float* __restrict__ mask,
                            float* __restrict__ ysum) {
    int idx = blockIdx.x * blockDim.x + threadIdx.x;
    if (idx < BATCH * OUT_DIM) ysum[idx] = 0.f;
    if (idx < IN_DIM * OUT_DIM) {
        int i = idx >> 8;
        int o = idx & 255;
        float m = mask[idx];
        g_sbT[o * IN_DIM + i] = m * sb[idx];
        g_ssT[o * IN_DIM + i] = m * ssp[idx];
    }
}

__device__ __forceinline__ void cp_async16(unsigned int saddr, const void* gaddr) {
    asm volatile("cp.async.cg.shared.global [%0], [%1], 16;\n"
                 :: "r"(saddr), "l"(gaddr));
}
__device__ __forceinline__ void cp_async_wait_all() {
    asm volatile("cp.async.commit_group;\ncp.async.wait_group 0;\n" ::: "memory");
}

__global__ __launch_bounds__(THREADS, 2)
void kan_kernel(const float* __restrict__ x,
                const float* __restrict__ grid,
                const float* __restrict__ coef,
                float* __restrict__ out) {
    // coef slab: [i][chunk] rows of 32 floats, XOR swizzle chunk ^ ((i>>2)&7)
    __shared__ float s_coef[IN_DIM * OT * NB];   // 32 KB
    __shared__ float s_sb[OT * IN_DIM];          // 4 KB
    __shared__ float s_ss[OT * IN_DIM];          // 4 KB

    const int tid  = threadIdx.x;
    const int quad = tid & 63;
    const int bg   = tid >> 6;
    const int i0   = quad << 2;
    const int b0   = blockIdx.x * BT + bg * 2;

    // ---- B-spline basis for 2 batches x 4 dims (registers) ----
    float4 x4[2];
    x4[0] = *reinterpret_cast<const float4*>(x + (size_t)b0 * IN_DIM + i0);
    x4[1] = *reinterpret_cast<const float4*>(x + (size_t)(b0 + 1) * IN_DIM + i0);
    float xs[2][4] = {{x4[0].x, x4[0].y, x4[0].z, x4[0].w},
                      {x4[1].x, x4[1].y, x4[1].z, x4[1].w}};

    float bsp[2][NB][4];
    #pragma unroll
    for (int ii = 0; ii < 4; ii++) {
        const float* gr = grid + (size_t)(i0 + ii) * GRIDN;
        float g[GRIDN];
        #pragma unroll
        for (int j = 0; j < GRIDN; j++) g[j] = gr[j];
        #pragma unroll
        for (int bb = 0; bb < 2; bb++) {
            float xv = xs[bb][ii];
            float B[GRIDN - 1];
            #pragma unroll
            for (int j = 0; j < GRIDN - 1; j++)
                B[j] = (xv >= g[j] && xv < g[j + 1]) ? 1.f : 0.f;
            #pragma unroll
            for (int ki = 1; ki <= 3; ki++) {
                #pragma unroll
                for (int j = 0; j < GRIDN - 1; j++) {
                    if (j < GRIDN - 1 - ki) {
                        float left  = (xv - g[j]) / (g[j + ki] - g[j]);
                        float right = (g[j + ki + 1] - xv) / (g[j + ki + 1] - g[j + 1]);
                        B[j] = left * B[j] + right * B[j + 1];
                    }
                }
            }
            #pragma unroll
            for (int k = 0; k < NB; k++) bsp[bb][k][ii] = B[k];
        }
    }

    float base[2][4];
    #pragma unroll
    for (int bb = 0; bb < 2; bb++)
        #pragma unroll
        for (int ii = 0; ii < 4; ii++) {
            float xv = xs[bb][ii];
            base[bb][ii] = xv / (1.f + __expf(-xv));
        }

    float* ysum     = out;
    float* preacts  = out + (size_t)BATCH * OUT_DIM;
    float* postacts = preacts  + (size_t)BATCH * OUT_DIM * IN_DIM;
    float* postspl  = postacts + (size_t)BATCH * OUT_DIM * IN_DIM;

    const size_t rowbase0 = (size_t)b0 * OUT_DIM * IN_DIM + i0;
    const int mysw = quad & 7;

    // Shared-address bases for cp.async
    const unsigned int s_coef_b = (unsigned int)__cvta_generic_to_shared(s_coef);
    const unsigned int s_sb_b   = (unsigned int)__cvta_generic_to_shared(s_sb);
    const unsigned int s_ss_b   = (unsigned int)__cvta_generic_to_shared(s_ss);

    for (int T = 0; T < NT; T++) {
        __syncthreads();   // previous tile's reads complete

        // coef fill: coalesced 16B cp.async, swizzled dst
        #pragma unroll
        for (int r = 0; r < 8; r++) {
            int c = tid + THREADS * r;          // 0..2047
            int i = c >> 3;
            int q = c & 7;
            const float* src = coef + (size_t)i * (OUT_DIM * NB) + T * (OT * NB) + q * 4;
            int qs = q ^ ((i >> 2) & 7);
            cp_async16(s_coef_b + (unsigned int)((i * 32 + (qs << 2)) * 4), src);
        }
        // scale fill: 1 x 16B per array per thread
        {
            int ol = tid >> 6;
            int ic = (tid & 63) << 2;
            int o  = T * OT + ol;
            cp_async16(s_sb_b + (unsigned int)((ol * IN_DIM + ic) * 4),
                       g_sbT + (size_t)o * IN_DIM + ic);
            cp_async16(s_ss_b + (unsigned int)((ol * IN_DIM + ic) * 4),
                       g_ssT + (size_t)o * IN_DIM + ic);
        }
        cp_async_wait_all();
        __syncthreads();

        #pragma unroll
        for (int ol = 0; ol < OT; ol++) {
            const int o = T * OT + ol;

            float y[2][4];
            #pragma unroll
            for (int bb = 0; bb < 2; bb++)
                #pragma unroll
                for (int ii = 0; ii < 4; ii++) y[bb][ii] = 0.f;

            #pragma unroll
            for (int ii = 0; ii < 4; ii++) {
                const int i = i0 + ii;
                float4 ca = *reinterpret_cast<const float4*>(
                    s_coef + i * 32 + (((2 * ol)     ^ mysw) << 2));
                float4 cb = *reinterpret_cast<const float4*>(
                    s_coef + i * 32 + (((2 * ol + 1) ^ mysw) << 2));
                #pragma unroll
                for (int bb = 0; bb < 2; bb++) {
                    float acc;
                    acc  = ca.x * bsp[bb][0][ii];
                    acc += ca.y * bsp[bb][1][ii];
                    acc += ca.z * bsp[bb][2][ii];
                    acc += ca.w * bsp[bb][3][ii];
                    acc += cb.x * bsp[bb][4][ii];
                    acc += cb.y * bsp[bb][5][ii];
                    acc += cb.z * bsp[bb][6][ii];
                    acc += cb.w * bsp[bb][7][ii];
                    y[bb][ii] = acc;
                }
            }

            float4 sb4 = *reinterpret_cast<const float4*>(s_sb + ol * IN_DIM + i0);
            float4 ss4 = *reinterpret_cast<const float4*>(s_ss + ol * IN_DIM + i0);

            #pragma unroll
            for (int bb = 0; bb < 2; bb++) {
                float4 y4  = make_float4(y[bb][0], y[bb][1], y[bb][2], y[bb][3]);
                float4 yy4;
                yy4.x = sb4.x * base[bb][0] + ss4.x * y4.x;
                yy4.y = sb4.y * base[bb][1] + ss4.y * y4.y;
                yy4.z = sb4.z * base[bb][2] + ss4.z * y4.z;
                yy4.w = sb4.w * base[bb][3] + ss4.w * y4.w;

                size_t off = rowbase0 + (size_t)bb * (OUT_DIM * IN_DIM)
                                      + (size_t)o * IN_DIM;
                // Streaming (evict-first) stores: write-once data, keep L2 for coef
                __stcs(reinterpret_cast<float4*>(postspl  + off), y4);
                __stcs(reinterpret_cast<float4*>(postacts + off), yy4);
                __stcs(reinterpret_cast<float4*>(preacts  + off), x4[bb]);

                // y_sum: warp butterfly (redux.f32 not available on sm_103)
                float s = (yy4.x + yy4.y) + (yy4.z + yy4.w);
                #pragma unroll
                for (int d = 16; d > 0; d >>= 1)
                    s += __shfl_xor_sync(0xffffffffu, s, d);
                if ((tid & 31) == 0)
                    atomicAdd(ysum + (size_t)(b0 + bb) * OUT_DIM + o, s);
            }
        }
    }
}

extern "C" void kernel_launch(void* const* d_in, const int* in_sizes, int n_in,
                              void* d_out, int out_size) {
    const float* x     = (const float*)d_in[0];
    const float* grid  = (const float*)d_in[1];
    const float* coef  = (const float*)d_in[2];
    const float* sb    = (const float*)d_in[3];
    const float* ssp   = (const float*)d_in[4];
    const float* mask  = (const float*)d_in[5];
    float* out = (float*)d_out;

    (void)in_sizes; (void)n_in; (void)out_size;

    int n = BATCH * OUT_DIM;   // covers both the zero region and prep range
    init_kernel<<<(n + 255) / 256, 256>>>(sb, ssp, mask, out);
    kan_kernel<<<BATCH / BT, THREADS>>>(x, grid, coef, out);
}